// round 3
// baseline (speedup 1.0000x reference)
#include <cuda_runtime.h>
#include <cuda_bf16.h>
#include <cstdint>

#define MAX_N 100000

// Device scratch (no cudaMalloc allowed).
__device__ float g_diag[MAX_N];
__device__ float g_deg[MAX_N];

// ---------------------------------------------------------------------------
// K0: zero the degree accumulator
// ---------------------------------------------------------------------------
__global__ void zero_deg_kernel(int n) {
    int i = blockIdx.x * blockDim.x + threadIdx.x;
    if (i < n) g_deg[i] = 0.0f;
}

// ---------------------------------------------------------------------------
// K1: diag[i] = sigmoid(x[i,:] . w + b)   (warp per row, D=256)
// blockDim = 256 (8 warps -> 8 rows per block)
// ---------------------------------------------------------------------------
__global__ void diag_kernel(const float* __restrict__ x,
                            const float* __restrict__ w,
                            const float* __restrict__ b,
                            int n, int d) {
    __shared__ float sw[256];
    if (threadIdx.x < d) sw[threadIdx.x] = w[threadIdx.x];
    __syncthreads();

    int warp = threadIdx.x >> 5;
    int lane = threadIdx.x & 31;
    int row  = blockIdx.x * 8 + warp;
    if (row >= n) return;

    const float4* xr = reinterpret_cast<const float4*>(x + (size_t)row * d);
    const float4* wf = reinterpret_cast<const float4*>(sw);

    float acc = 0.0f;
    // d = 256 -> 64 float4 across 32 lanes -> 2 iterations
    #pragma unroll
    for (int it = 0; it < 2; ++it) {
        float4 xv = xr[lane + it * 32];
        float4 wv = wf[lane + it * 32];
        acc += xv.x * wv.x + xv.y * wv.y + xv.z * wv.z + xv.w * wv.w;
    }
    #pragma unroll
    for (int off = 16; off > 0; off >>= 1)
        acc += __shfl_xor_sync(0xFFFFFFFFu, acc, off);

    if (lane == 0) {
        float z = acc + b[0];
        g_diag[row] = 1.0f / (1.0f + expf(-z));
    }
}

// ---------------------------------------------------------------------------
// K2: degree histogram over col = edge_index[1]  (int32 indices)
// 4 edges per thread via int4 loads.
// ---------------------------------------------------------------------------
__global__ void deg_kernel(const int* __restrict__ col, int E, int n) {
    int i = blockIdx.x * blockDim.x + threadIdx.x;
    int base = i * 4;
    if (base + 3 < E) {
        int4 c = *reinterpret_cast<const int4*>(col + base);
        if ((unsigned)c.x < (unsigned)n) atomicAdd(&g_deg[c.x], 1.0f);
        if ((unsigned)c.y < (unsigned)n) atomicAdd(&g_deg[c.y], 1.0f);
        if ((unsigned)c.z < (unsigned)n) atomicAdd(&g_deg[c.z], 1.0f);
        if ((unsigned)c.w < (unsigned)n) atomicAdd(&g_deg[c.w], 1.0f);
    } else {
        for (int k = base; k < E; ++k) {
            int c = col[k];
            if ((unsigned)c < (unsigned)n) atomicAdd(&g_deg[c], 1.0f);
        }
    }
}

// ---------------------------------------------------------------------------
// K3: adj_val[e] = (1/deg[row]) * edge_attr[e] * diag[col]
// Optionally also writes edge_index (cast to float) for tuple output layout.
// ---------------------------------------------------------------------------
__global__ void final_kernel(const int* __restrict__ row_idx,
                             const int* __restrict__ col_idx,
                             const float* __restrict__ edge_attr,
                             float* __restrict__ out,
                             int E, int n, int write_index) {
    int i = blockIdx.x * blockDim.x + threadIdx.x;
    if (i >= E) return;

    int r = row_idx[i];
    int c = col_idx[i];
    float dinv = 0.0f, dg = 0.0f;
    if ((unsigned)r < (unsigned)n) { dg = g_deg[r]; }
    if ((unsigned)c < (unsigned)n) { dinv = g_diag[c]; }
    float v = (edge_attr[i] * dinv) / dg;

    if (write_index) {
        out[i]         = (float)r;
        out[E + i]     = (float)c;
        out[2 * E + i] = v;
    } else {
        out[i] = v;
    }
}

// ---------------------------------------------------------------------------
// launch
// inputs (metadata order): x [N*D] f32, edge_index [2*E] i32 (narrowed i64),
//                          edge_attr [E] f32, w [D] f32, b [1] f32
// ---------------------------------------------------------------------------
extern "C" void kernel_launch(void* const* d_in, const int* in_sizes, int n_in,
                              void* d_out, int out_size) {
    const float* x          = (const float*)d_in[0];
    const int*   edge_index = (const int*)d_in[1];
    const float* edge_attr  = (const float*)d_in[2];
    const float* w          = (const float*)d_in[3];
    const float* b          = (const float*)d_in[4];
    float*       out        = (float*)d_out;

    int D = in_sizes[3];
    int N = in_sizes[0] / D;
    int E = in_sizes[2];

    const int* row_idx = edge_index;
    const int* col_idx = edge_index + E;

    // K0: zero degrees
    zero_deg_kernel<<<(N + 255) / 256, 256>>>(N);

    // K1: diag = sigmoid(x @ w + b), warp per row
    diag_kernel<<<(N + 7) / 8, 256>>>(x, w, b, N, D);

    // K2: degree histogram (4 edges/thread)
    int t2 = (E + 3) / 4;
    deg_kernel<<<(t2 + 255) / 256, 256>>>(col_idx, E, N);

    // K3: final edge values (+ optional edge_index passthrough)
    int write_index = (out_size >= 3 * E) ? 1 : 0;
    final_kernel<<<(E + 255) / 256, 256>>>(row_idx, col_idx, edge_attr, out,
                                           E, N, write_index);
}

// round 4
// speedup vs baseline: 1.0284x; 1.0284x over previous
#include <cuda_runtime.h>
#include <cuda_bf16.h>
#include <cstdint>

#define MAX_N 100000

// Device scratch (no cudaMalloc allowed).
__device__ float g_diag[MAX_N];
__device__ float g_deg[MAX_N];   // degree, then overwritten with 1/degree

// ---------------------------------------------------------------------------
// K0: zero the degree accumulator
// ---------------------------------------------------------------------------
__global__ void zero_deg_kernel(int n) {
    int i = blockIdx.x * blockDim.x + threadIdx.x;
    if (i < n) g_deg[i] = 0.0f;
}

// ---------------------------------------------------------------------------
// K1 (fused): blocks [0, diag_blocks) compute diag = sigmoid(x@w+b)
//             blocks [diag_blocks, ...) compute degree histogram
// The two halves touch different pipes (DRAM stream vs L2 atomics) and
// overlap when co-resident.
// ---------------------------------------------------------------------------
__global__ void diag_deg_kernel(const float* __restrict__ x,
                                const float* __restrict__ w,
                                const float* __restrict__ b,
                                int n, int d, int diag_blocks,
                                const int* __restrict__ col, int E) {
    if ((int)blockIdx.x < diag_blocks) {
        // ---- diag: warp per row, D=256 ----
        __shared__ float sw[256];
        if (threadIdx.x < d) sw[threadIdx.x] = w[threadIdx.x];
        __syncthreads();

        int warp = threadIdx.x >> 5;
        int lane = threadIdx.x & 31;
        int row  = blockIdx.x * 8 + warp;
        if (row >= n) return;

        const float4* xr = reinterpret_cast<const float4*>(x + (size_t)row * d);
        const float4* wf = reinterpret_cast<const float4*>(sw);

        float acc = 0.0f;
        #pragma unroll
        for (int it = 0; it < 2; ++it) {
            float4 xv = xr[lane + it * 32];
            float4 wv = wf[lane + it * 32];
            acc += xv.x * wv.x + xv.y * wv.y + xv.z * wv.z + xv.w * wv.w;
        }
        #pragma unroll
        for (int off = 16; off > 0; off >>= 1)
            acc += __shfl_xor_sync(0xFFFFFFFFu, acc, off);

        if (lane == 0) {
            float z = acc + b[0];
            g_diag[row] = 1.0f / (1.0f + expf(-z));
        }
    } else {
        // ---- degree histogram: 4 edges per thread, int4 loads ----
        int tb   = blockIdx.x - diag_blocks;
        int i    = tb * blockDim.x + threadIdx.x;
        int base = i * 4;
        if (base + 3 < E) {
            int4 c = *reinterpret_cast<const int4*>(col + base);
            atomicAdd(&g_deg[c.x], 1.0f);
            atomicAdd(&g_deg[c.y], 1.0f);
            atomicAdd(&g_deg[c.z], 1.0f);
            atomicAdd(&g_deg[c.w], 1.0f);
        } else {
            for (int k = base; k < E; ++k)
                atomicAdd(&g_deg[col[k]], 1.0f);
        }
    }
}

// ---------------------------------------------------------------------------
// K2: g_deg <- 1/g_deg (in place), so the final pass multiplies instead of
// dividing.
// ---------------------------------------------------------------------------
__global__ void recip_deg_kernel(int n) {
    int i = blockIdx.x * blockDim.x + threadIdx.x;
    if (i < n) g_deg[i] = 1.0f / g_deg[i];
}

// ---------------------------------------------------------------------------
// K3: adj_val[e] = deginv[row] * edge_attr[e] * diag[col]
// 4 edges per thread: int4/float4 loads, float4 stores, 8 independent
// gathers per thread for memory-level parallelism.
// ---------------------------------------------------------------------------
__global__ void final_kernel(const int* __restrict__ row_idx,
                             const int* __restrict__ col_idx,
                             const float* __restrict__ edge_attr,
                             float* __restrict__ out,
                             int E, int write_index) {
    int i    = blockIdx.x * blockDim.x + threadIdx.x;
    int base = i * 4;

    if (base + 3 < E) {
        int4   r4 = *reinterpret_cast<const int4*>(row_idx + base);
        int4   c4 = *reinterpret_cast<const int4*>(col_idx + base);
        float4 a4 = *reinterpret_cast<const float4*>(edge_attr + base);

        // 8 independent gathers (L2-resident tables)
        float di0 = g_deg[r4.x],  di1 = g_deg[r4.y];
        float di2 = g_deg[r4.z],  di3 = g_deg[r4.w];
        float dg0 = g_diag[c4.x], dg1 = g_diag[c4.y];
        float dg2 = g_diag[c4.z], dg3 = g_diag[c4.w];

        float4 v;
        v.x = a4.x * dg0 * di0;
        v.y = a4.y * dg1 * di1;
        v.z = a4.z * dg2 * di2;
        v.w = a4.w * dg3 * di3;

        if (write_index) {
            float4 fr = make_float4((float)r4.x, (float)r4.y,
                                    (float)r4.z, (float)r4.w);
            float4 fc = make_float4((float)c4.x, (float)c4.y,
                                    (float)c4.z, (float)c4.w);
            *reinterpret_cast<float4*>(out + base)         = fr;
            *reinterpret_cast<float4*>(out + E + base)     = fc;
            *reinterpret_cast<float4*>(out + 2 * E + base) = v;
        } else {
            *reinterpret_cast<float4*>(out + base) = v;
        }
    } else {
        for (int k = base; k < E; ++k) {
            int r = row_idx[k];
            int c = col_idx[k];
            float v = edge_attr[k] * g_diag[c] * g_deg[r];
            if (write_index) {
                out[k]         = (float)r;
                out[E + k]     = (float)c;
                out[2 * E + k] = v;
            } else {
                out[k] = v;
            }
        }
    }
}

// ---------------------------------------------------------------------------
// launch
// inputs (metadata order): x [N*D] f32, edge_index [2*E] i32 (narrowed i64),
//                          edge_attr [E] f32, w [D] f32, b [1] f32
// ---------------------------------------------------------------------------
extern "C" void kernel_launch(void* const* d_in, const int* in_sizes, int n_in,
                              void* d_out, int out_size) {
    const float* x          = (const float*)d_in[0];
    const int*   edge_index = (const int*)d_in[1];
    const float* edge_attr  = (const float*)d_in[2];
    const float* w          = (const float*)d_in[3];
    const float* b          = (const float*)d_in[4];
    float*       out        = (float*)d_out;

    int D = in_sizes[3];
    int N = in_sizes[0] / D;
    int E = in_sizes[2];

    const int* row_idx = edge_index;
    const int* col_idx = edge_index + E;

    // K0: zero degrees
    zero_deg_kernel<<<(N + 255) / 256, 256>>>(N);

    // K1: fused diag + degree histogram
    int diag_blocks = (N + 7) / 8;
    int deg_threads = (E + 3) / 4;
    int deg_blocks  = (deg_threads + 255) / 256;
    diag_deg_kernel<<<diag_blocks + deg_blocks, 256>>>(
        x, w, b, N, D, diag_blocks, col_idx, E);

    // K2: reciprocal of degree
    recip_deg_kernel<<<(N + 255) / 256, 256>>>(N);

    // K3: final edge values (+ optional edge_index passthrough), 4/thread
    int write_index = (out_size >= 3 * E) ? 1 : 0;
    int fin_threads = (E + 3) / 4;
    final_kernel<<<(fin_threads + 255) / 256, 256>>>(
        row_idx, col_idx, edge_attr, out, E, write_index);
}